// round 15
// baseline (speedup 1.0000x reference)
#include <cuda_runtime.h>
#include <cuda_bf16.h>
#include <cuda_fp16.h>
#include <math.h>
#include <stdint.h>

#define NB 64
#define NTT 256
#define NU 1024
#define KX 2048
#define N3 3072
#define NBLK 128

// ------------------------- device scratch (no allocs allowed) ----------------
__device__ __align__(16) uint4 g_AF[(size_t)1024 * 128 * 32];   // A frag-major f16 (64MB)
__device__ __align__(16) uint2 g_WF[(size_t)384 * 128 * 32];    // W frag-major f16 (12.6MB)
__device__ __align__(16) float g_G[(size_t)NTT * NB * N3];
__device__ __align__(16) uint4 g_UrzF[256 * 64 * 32];           // frag-packed [U_r|U_z] f16 hi/lo
__device__ __align__(16) uint4 g_UcF[128 * 64 * 32];            // frag-packed U f16 hi/lo
__device__ __align__(16) uint4 g_hF[4 * 64 * 32];               // h as f16 A-fragments (128KB)
__device__ __align__(16) uint4 g_a2F[4 * 64 * 32];              // a2 as f16 A-fragments
__device__ __align__(16) float g_h[NB * NU];
__device__ __align__(16) float g_z[NB * NU];

// ---- hierarchical grid barrier state (monotonic generation) -----------------
// 8 sub-counters on distinct 128B lines (16 CTAs each) -> 1 root -> generation.
// Same-address L2 atomic serialization drops 128x32cyc -> ~16x32 + 8x32 cyc.
__device__ __align__(128) unsigned g_cnt_sub[8][32];   // [s][0] used, rest padding
__device__ __align__(128) unsigned g_root = 0;
__device__ __align__(128) unsigned g_gen = 0;

__device__ __forceinline__ void grid_bar(int bx) {
    __syncthreads();
    if (threadIdx.x == 0) {
        unsigned gen = *((volatile unsigned*)&g_gen);
        __threadfence();
        if (atomicAdd(&g_cnt_sub[bx & 7][0], 1u) == 15u) {       // last of 16 in sub-group
            g_cnt_sub[bx & 7][0] = 0;                            // safe pre-flip reset
            if (atomicAdd(&g_root, 1u) == 7u) {                  // last sub-group
                g_root = 0;
                __threadfence();
                atomicAdd(&g_gen, 1u);
            }
        }
        if (*((volatile unsigned*)&g_gen) == gen) {
            unsigned spins = 0;
            while (*((volatile unsigned*)&g_gen) == gen) {
                if (++spins > 4096u) __nanosleep(40);
                if (spins > 4000000u) break;   // safety valve: never hang
            }
        }
        __threadfence();
    }
    __syncthreads();
}

// ------------------------- mma.sync helpers (sm_80+ ISA) ---------------------
#define MMA_F16(d, a0, a1, a2, a3, b0, b1) \
    asm volatile("mma.sync.aligned.m16n8k16.row.col.f32.f16.f16.f32 " \
                 "{%0,%1,%2,%3}, {%4,%5,%6,%7}, {%8,%9}, {%0,%1,%2,%3};" \
                 : "+f"((d)[0]), "+f"((d)[1]), "+f"((d)[2]), "+f"((d)[3]) \
                 : "r"(a0), "r"(a1), "r"(a2), "r"(a3), "r"(b0), "r"(b1))

static __device__ __forceinline__ uint32_t pack2hf(float x, float y) {
    __half2 v = {__float2half(x), __float2half(y)};
    return *(uint32_t*)&v;
}
static __device__ __forceinline__ uint32_t pack2lf(float x, float y) {
    float hx = __half2float(__float2half(x));
    float hy = __half2float(__float2half(y));
    __half2 v = {__float2half(x - hx), __float2half(y - hy)};
    return *(uint32_t*)&v;
}
static __device__ __forceinline__ float hsig(float x) {
    return fminf(fmaxf(0.2f * x + 0.5f, 0.0f), 1.0f);
}

// ------------------------- packing / init -----------------------------------
__global__ void pack_AF(const float* __restrict__ all) {
    int fid = blockIdx.x * blockDim.x + threadIdx.x;   // 4194304
    int lane = fid & 31, kc = (fid >> 5) & 127, m16t = fid >> 12;
    int row = m16t * 16 + (lane >> 2);
    int col = kc * 16 + (lane & 3) * 2;
    const float* p = all + (size_t)row * KX + col;
    g_AF[fid] = make_uint4(pack2hf(p[0], p[1]),
                           pack2hf(p[8 * KX], p[8 * KX + 1]),
                           pack2hf(p[8], p[9]),
                           pack2hf(p[8 * KX + 8], p[8 * KX + 9]));
}

__global__ void pack_WF(const float* __restrict__ Wr, const float* __restrict__ Cr,
                        const float* __restrict__ Wz, const float* __restrict__ Cz,
                        const float* __restrict__ Wc, const float* __restrict__ Cc) {
    int fid = blockIdx.x * blockDim.x + threadIdx.x;   // 1572864
    int lane = fid & 31, kc = (fid >> 5) & 127, n8t = fid >> 12;
    int n = n8t * 8 + (lane >> 2);
    int k0 = kc * 16 + (lane & 3) * 2;
    int sel = n >> 10, j = n & 1023;
    const float* C = (sel == 0) ? Cr : (sel == 1) ? Cz : Cc;
    const float* W = (sel == 0) ? Wr : (sel == 1) ? Wz : Wc;
    auto wat = [&](int k) -> float {
        return (k < 1024) ? C[k * NU + j] : W[(k - 1024) * NU + j];
    };
    g_WF[fid] = make_uint2(pack2hf(wat(k0), wat(k0 + 1)),
                           pack2hf(wat(k0 + 8), wat(k0 + 9)));
}

__global__ void pack_UrzF(const float* __restrict__ Ur, const float* __restrict__ Uz) {
    int fid = blockIdx.x * blockDim.x + threadIdx.x;   // 524288
    int nt = fid >> 11, kc = (fid >> 5) & 63, lane = fid & 31;
    int n = nt * 8 + (lane >> 2);
    int k0 = kc * 16 + (lane & 3) * 2;
    const float* src = (n < 1024) ? Ur : Uz;
    int nn = n & 1023;
    float v00 = src[(k0 + 0) * NU + nn], v01 = src[(k0 + 1) * NU + nn];
    float v10 = src[(k0 + 8) * NU + nn], v11 = src[(k0 + 9) * NU + nn];
    g_UrzF[fid] = make_uint4(pack2hf(v00, v01), pack2hf(v10, v11),
                             pack2lf(v00, v01), pack2lf(v10, v11));
}

__global__ void pack_UcF(const float* __restrict__ Uc) {
    int fid = blockIdx.x * blockDim.x + threadIdx.x;   // 262144
    int nt = fid >> 11, kc = (fid >> 5) & 63, lane = fid & 31;
    int n = nt * 8 + (lane >> 2);
    int k0 = kc * 16 + (lane & 3) * 2;
    float v00 = Uc[(k0 + 0) * NU + n], v01 = Uc[(k0 + 1) * NU + n];
    float v10 = Uc[(k0 + 8) * NU + n], v11 = Uc[(k0 + 9) * NU + n];
    g_UcF[fid] = make_uint4(pack2hf(v00, v01), pack2hf(v10, v11),
                            pack2lf(v00, v01), pack2lf(v10, v11));
}

__global__ void pack_h_init(const float* __restrict__ h0) {
    int i = blockIdx.x * blockDim.x + threadIdx.x;     // 65536
    if (i < NB * NU) g_h[i] = h0[i];
    if (i < 4 * 64 * 32) {                              // h fragments
        int lane = i & 31, kc = (i >> 5) & 63, m16t = i >> 11;
        int r0 = m16t * 16 + (lane >> 2);
        int c0 = kc * 16 + (lane & 3) * 2;
        g_hF[i] = make_uint4(
            pack2hf(h0[r0 * NU + c0],           h0[r0 * NU + c0 + 1]),
            pack2hf(h0[(r0 + 8) * NU + c0],     h0[(r0 + 8) * NU + c0 + 1]),
            pack2hf(h0[r0 * NU + c0 + 8],       h0[r0 * NU + c0 + 9]),
            pack2hf(h0[(r0 + 8) * NU + c0 + 8], h0[(r0 + 8) * NU + c0 + 9]));
    }
}

// ------------------------- frag-direct precompute GEMM (single f16) ----------
__global__ __launch_bounds__(256) void gemm_pre_f() {
    const int tid = threadIdx.x;
    const int wid = tid >> 5, lane = tid & 31;
    const int wm = wid >> 2, wn = wid & 3;
    const int bn = blockIdx.x, bm = blockIdx.y;

    float acc[4][4][4];
#pragma unroll
    for (int i = 0; i < 4; i++)
#pragma unroll
        for (int j = 0; j < 4; j++)
#pragma unroll
            for (int k = 0; k < 4; k++) acc[i][j][k] = 0.0f;

    const uint4* ap = g_AF + ((size_t)(bm * 8 + wm * 4) * 128) * 32 + lane;
    const uint2* bp = g_WF + ((size_t)(bn * 16 + wn * 4) * 128) * 32 + lane;

    for (int kc = 0; kc < 128; kc++) {
        uint4 af[4];
        uint2 bf[4];
#pragma unroll
        for (int mi = 0; mi < 4; mi++) af[mi] = ap[(size_t)(mi * 128 + kc) * 32];
#pragma unroll
        for (int ni = 0; ni < 4; ni++) bf[ni] = bp[(size_t)(ni * 128 + kc) * 32];
#pragma unroll
        for (int mi = 0; mi < 4; mi++)
#pragma unroll
            for (int ni = 0; ni < 4; ni++)
                MMA_F16(acc[mi][ni], af[mi].x, af[mi].y, af[mi].z, af[mi].w,
                        bf[ni].x, bf[ni].y);
    }

#pragma unroll
    for (int mi = 0; mi < 4; mi++) {
        int mA = bm * 128 + wm * 64 + mi * 16 + (lane >> 2);
        int mB = mA + 8;
        int bA = mA >> 8, tA = mA & 255;
        int bB = mB >> 8, tB = mB & 255;
        float* oA = g_G + (size_t)(tA * NB + bA) * N3;
        float* oB = g_G + (size_t)(tB * NB + bB) * N3;
        int colb = bn * 128 + wn * 32 + (lane & 3) * 2;
#pragma unroll
        for (int ni = 0; ni < 4; ni++) {
            int c = colb + ni * 8;
            *(float2*)(oA + c) = make_float2(acc[mi][ni][0], acc[mi][ni][1]);
            *(float2*)(oB + c) = make_float2(acc[mi][ni][2], acc[mi][ni][3]);
        }
    }
}

// ------------------------- persistent recurrent kernel -----------------------
// Identical math to R14; only the grid barrier internals changed.
__global__ __launch_bounds__(256, 1) void recurrent(float* __restrict__ out) {
    extern __shared__ __align__(16) uint4 dsm[];
    uint4* sU = dsm;                                   // [0,2048): b0, [2048,4096): b1, [4096,6144): uc
    float* sred = (float*)(dsm + 6144);                // 8KB reduce buffer
    const int bx = blockIdx.x;
    const int tid = threadIdx.x;
    const int wid = tid >> 5, lane = tid & 31;
    const int wm = wid >> 1, ws = wid & 1;
    const int erow = wm * 16 + (lane >> 2);
    const int ecol2 = (lane & 3) * 2;
    const int eb = tid >> 2, ejp = tid & 3;            // phase B final mapping

    // ---- stage U fragments into smem (once) ----
    {
        const uint4* u0 = g_UrzF + (size_t)(bx * 2 + 0) * 2048;
        const uint4* u1 = g_UrzF + (size_t)(bx * 2 + 1) * 2048;
        const uint4* uc = g_UcF + (size_t)bx * 2048;
#pragma unroll
        for (int i = 0; i < 8; i++) {
            int idx = i * 256 + tid;
            sU[idx] = u0[idx];
            sU[2048 + idx] = u1[idx];
            sU[4096 + idx] = uc[idx];
        }
    }
    __syncthreads();

    const int colg = bx * 16 + ws * 8 + ecol2;
    const int j0 = bx * 8 + ejp * 2;
    float2 G0 = *(const float2*)&g_G[((size_t)0 * NB + erow) * N3 + colg];
    float2 G1 = *(const float2*)&g_G[((size_t)0 * NB + erow + 8) * N3 + colg];

    for (int t = 0; t < NTT; t++) {
        // ===== phase A: h @ [U_r|U_z], K-split over ws, fused act_rz =========
        float2 Gc, hv;
        {
            const uint4* afr = g_hF + (wm * 64) * 32 + lane;
            float2 h0v = make_float2(0.f, 0.f), h1v = make_float2(0.f, 0.f);
            if (bx < 64) {
                h0v = __ldcg((const float2*)&g_h[erow * NU + colg]);
                h1v = __ldcg((const float2*)&g_h[(erow + 8) * NU + colg]);
            }
            float a0h[4] = {0.f, 0.f, 0.f, 0.f}, a0l[4] = {0.f, 0.f, 0.f, 0.f};
            float a1h[4] = {0.f, 0.f, 0.f, 0.f}, a1l[4] = {0.f, 0.f, 0.f, 0.f};
#pragma unroll 4
            for (int kc = 0; kc < 32; kc++) {
                int kk = ws * 32 + kc;
                uint4 av = __ldcg(&afr[kk * 32]);
                uint4 v0 = sU[kk * 32 + lane];
                uint4 v1 = sU[2048 + kk * 32 + lane];
                MMA_F16(a0h, av.x, av.y, av.z, av.w, v0.x, v0.y);
                MMA_F16(a0l, av.x, av.y, av.z, av.w, v0.z, v0.w);
                MMA_F16(a1h, av.x, av.y, av.z, av.w, v1.x, v1.y);
                MMA_F16(a1l, av.x, av.y, av.z, av.w, v1.z, v1.w);
            }
            *(float4*)&sred[((wm * 2 + 0) * 2 + ws) * 128 + lane * 4] =
                make_float4(a0h[0] + a0l[0], a0h[1] + a0l[1],
                            a0h[2] + a0l[2], a0h[3] + a0l[3]);
            *(float4*)&sred[((wm * 2 + 1) * 2 + ws) * 128 + lane * 4] =
                make_float4(a1h[0] + a1l[0], a1h[1] + a1l[1],
                            a1h[2] + a1l[2], a1h[3] + a1l[3]);
            __syncthreads();
            float4 p0 = *(const float4*)&sred[((wm * 2 + ws) * 2 + 0) * 128 + lane * 4];
            float4 p1 = *(const float4*)&sred[((wm * 2 + ws) * 2 + 1) * 128 + lane * 4];
            float s00 = p0.x + p1.x + G0.x, s01 = p0.y + p1.y + G0.y;
            float s10 = p0.z + p1.z + G1.x, s11 = p0.w + p1.w + G1.y;
            if (bx < 64) {                              // r gate -> a2 frags
                float a0 = h0v.x * hsig(s00), a1 = h0v.y * hsig(s01);
                float a2v = h1v.x * hsig(s10), a3v = h1v.y * hsig(s11);
                uint2* dst = (uint2*)&g_a2F[(wm * 64 + bx) * 32 + lane];
                dst[ws] = make_uint2(pack2hf(a0, a1), pack2hf(a2v, a3v));
            } else {                                    // z gate
                int j = colg - 1024;
                *(float2*)&g_z[erow * NU + j] = make_float2(hsig(s00), hsig(s01));
                *(float2*)&g_z[(erow + 8) * NU + j] = make_float2(hsig(s10), hsig(s11));
            }
            Gc = *(const float2*)&g_G[((size_t)t * NB + eb) * N3 + 2048 + j0];
            hv = __ldcg((const float2*)&g_h[eb * NU + j0]);
        }
        grid_bar(bx);
        // ===== phase B: (h*r) @ U, cols bx*8..+8, fused act_h ================
        {
            const uint4* afr = g_a2F + (wm * 64) * 32 + lane;
            float2 zv = __ldcg((const float2*)&g_z[eb * NU + j0]);
            float ach[4] = {0.f, 0.f, 0.f, 0.f}, acl[4] = {0.f, 0.f, 0.f, 0.f};
#pragma unroll 8
            for (int kc = 0; kc < 32; kc++) {
                int kk = ws * 32 + kc;
                uint4 av = __ldcg(&afr[kk * 32]);
                uint4 bv = sU[4096 + kk * 32 + lane];
                MMA_F16(ach, av.x, av.y, av.z, av.w, bv.x, bv.y);
                MMA_F16(acl, av.x, av.y, av.z, av.w, bv.z, bv.w);
            }
            *(float2*)&sred[(ws * 64 + erow) * 8 + ecol2] =
                make_float2(ach[0] + acl[0], ach[1] + acl[1]);
            *(float2*)&sred[(ws * 64 + erow + 8) * 8 + ecol2] =
                make_float2(ach[2] + acl[2], ach[3] + acl[3]);
            __syncthreads();
            float s0 = sred[eb * 8 + ejp * 2]     + sred[(64 + eb) * 8 + ejp * 2]     + Gc.x;
            float s1 = sred[eb * 8 + ejp * 2 + 1] + sred[(64 + eb) * 8 + ejp * 2 + 1] + Gc.y;
            float hn0 = (1.0f - zv.x) * hv.x + zv.x * tanhf(s0);
            float hn1 = (1.0f - zv.y) * hv.y + zv.y * tanhf(s1);
            *(float2*)&g_h[eb * NU + j0] = make_float2(hn0, hn1);
            *(float2*)&out[((size_t)eb * NTT + t) * NU + j0] = make_float2(hn0, hn1);
            int comp = ((eb >> 3) & 1) | ((bx & 1) << 1);
            ((uint32_t*)&g_hF[((eb >> 4) * 64 + (bx >> 1)) * 32 + (((eb & 7) << 2) | ejp)])[comp]
                = pack2hf(hn0, hn1);
            int tn = (t + 1 < NTT) ? t + 1 : t;
            G0 = *(const float2*)&g_G[((size_t)tn * NB + erow) * N3 + colg];
            G1 = *(const float2*)&g_G[((size_t)tn * NB + erow + 8) * N3 + colg];
        }
        grid_bar(bx);
    }
}

// ------------------------- launch -------------------------------------------
#define REC_SMEM (6144 * 16 + 8192)

extern "C" void kernel_launch(void* const* d_in, const int* in_sizes, int n_in,
                              void* d_out, int out_size) {
    const float* all = (const float*)d_in[0];
    const float* h0  = (const float*)d_in[1];
    const float* Wr  = (const float*)d_in[2];
    const float* Ur  = (const float*)d_in[3];
    const float* Cr  = (const float*)d_in[4];
    const float* Wz  = (const float*)d_in[5];
    const float* Uz  = (const float*)d_in[6];
    const float* Cz  = (const float*)d_in[7];
    const float* Wc  = (const float*)d_in[8];
    const float* Uc  = (const float*)d_in[9];
    const float* Cc  = (const float*)d_in[10];
    float* out = (float*)d_out;

    static int smem_set = 0;
    if (!smem_set) {
        cudaFuncSetAttribute(recurrent, cudaFuncAttributeMaxDynamicSharedMemorySize, REC_SMEM);
        smem_set = 1;
    }

    pack_AF<<<16384, 256>>>(all);
    pack_WF<<<6144, 256>>>(Wr, Cr, Wz, Cz, Wc, Cc);
    pack_UrzF<<<2048, 256>>>(Ur, Uz);
    pack_UcF<<<1024, 256>>>(Uc);
    pack_h_init<<<256, 256>>>(h0);
    gemm_pre_f<<<dim3(24, 128), 256>>>();
    recurrent<<<NBLK, 256, REC_SMEM>>>(out);
}

// round 16
// speedup vs baseline: 1.1651x; 1.1651x over previous
#include <cuda_runtime.h>
#include <cuda_bf16.h>
#include <cuda_fp16.h>
#include <math.h>
#include <stdint.h>

#define NB 64
#define NTT 256
#define NU 1024
#define KX 2048
#define N3 3072
#define NBLK 128

// ------------------------- device scratch (no allocs allowed) ----------------
__device__ __align__(16) uint4 g_AF[(size_t)1024 * 128 * 32];   // A frag-major f16 (64MB)
__device__ __align__(16) uint2 g_WF[(size_t)384 * 128 * 32];    // W frag-major f16 (12.6MB)
__device__ __align__(16) float g_G[(size_t)NTT * NB * N3];
__device__ __align__(16) uint2 g_UrzF[256 * 64 * 32];           // frag-packed [U_r|U_z] f16 (4MB)
__device__ __align__(16) uint2 g_UcF[128 * 64 * 32];            // frag-packed U f16 (2MB)
__device__ __align__(16) uint4 g_hF[4 * 64 * 32];               // h as f16 A-fragments (128KB)
__device__ __align__(16) uint4 g_a2F[4 * 64 * 32];              // a2 as f16 A-fragments
__device__ __align__(16) float g_h[NB * NU];
__device__ __align__(16) float g_z[NB * NU];

// grid barrier state (flat, monotonic generation -> safe across graph replays)
__device__ unsigned g_cnt = 0;
__device__ unsigned g_gen = 0;

__device__ __forceinline__ void grid_bar() {
    __syncthreads();
    if (threadIdx.x == 0) {
        unsigned gen = *((volatile unsigned*)&g_gen);
        __threadfence();
        if (atomicAdd(&g_cnt, 1u) == NBLK - 1u) {
            g_cnt = 0;
            __threadfence();
            atomicAdd(&g_gen, 1u);
        } else {
            unsigned spins = 0;
            while (*((volatile unsigned*)&g_gen) == gen) {
                if (++spins > 4096u) __nanosleep(40);
                if (spins > 4000000u) break;   // safety valve: never hang
            }
        }
        __threadfence();
    }
    __syncthreads();
}

// ------------------------- mma.sync helpers (sm_80+ ISA) ---------------------
#define MMA_F16(d, a0, a1, a2, a3, b0, b1) \
    asm volatile("mma.sync.aligned.m16n8k16.row.col.f32.f16.f16.f32 " \
                 "{%0,%1,%2,%3}, {%4,%5,%6,%7}, {%8,%9}, {%0,%1,%2,%3};" \
                 : "+f"((d)[0]), "+f"((d)[1]), "+f"((d)[2]), "+f"((d)[3]) \
                 : "r"(a0), "r"(a1), "r"(a2), "r"(a3), "r"(b0), "r"(b1))

static __device__ __forceinline__ uint32_t pack2hf(float x, float y) {
    __half2 v = {__float2half(x), __float2half(y)};
    return *(uint32_t*)&v;
}
static __device__ __forceinline__ float hsig(float x) {
    return fminf(fmaxf(0.2f * x + 0.5f, 0.0f), 1.0f);
}

// ------------------------- packing / init -----------------------------------
__global__ void pack_AF(const float* __restrict__ all) {
    int fid = blockIdx.x * blockDim.x + threadIdx.x;   // 4194304
    int lane = fid & 31, kc = (fid >> 5) & 127, m16t = fid >> 12;
    int row = m16t * 16 + (lane >> 2);
    int col = kc * 16 + (lane & 3) * 2;
    const float* p = all + (size_t)row * KX + col;
    g_AF[fid] = make_uint4(pack2hf(p[0], p[1]),
                           pack2hf(p[8 * KX], p[8 * KX + 1]),
                           pack2hf(p[8], p[9]),
                           pack2hf(p[8 * KX + 8], p[8 * KX + 9]));
}

__global__ void pack_WF(const float* __restrict__ Wr, const float* __restrict__ Cr,
                        const float* __restrict__ Wz, const float* __restrict__ Cz,
                        const float* __restrict__ Wc, const float* __restrict__ Cc) {
    int fid = blockIdx.x * blockDim.x + threadIdx.x;   // 1572864
    int lane = fid & 31, kc = (fid >> 5) & 127, n8t = fid >> 12;
    int n = n8t * 8 + (lane >> 2);
    int k0 = kc * 16 + (lane & 3) * 2;
    int sel = n >> 10, j = n & 1023;
    const float* C = (sel == 0) ? Cr : (sel == 1) ? Cz : Cc;
    const float* W = (sel == 0) ? Wr : (sel == 1) ? Wz : Wc;
    auto wat = [&](int k) -> float {
        return (k < 1024) ? C[k * NU + j] : W[(k - 1024) * NU + j];
    };
    g_WF[fid] = make_uint2(pack2hf(wat(k0), wat(k0 + 1)),
                           pack2hf(wat(k0 + 8), wat(k0 + 9)));
}

__global__ void pack_UrzF(const float* __restrict__ Ur, const float* __restrict__ Uz) {
    int fid = blockIdx.x * blockDim.x + threadIdx.x;   // 524288
    int nt = fid >> 11, kc = (fid >> 5) & 63, lane = fid & 31;
    int n = nt * 8 + (lane >> 2);
    int k0 = kc * 16 + (lane & 3) * 2;
    const float* src = (n < 1024) ? Ur : Uz;
    int nn = n & 1023;
    g_UrzF[fid] = make_uint2(
        pack2hf(src[(k0 + 0) * NU + nn], src[(k0 + 1) * NU + nn]),
        pack2hf(src[(k0 + 8) * NU + nn], src[(k0 + 9) * NU + nn]));
}

__global__ void pack_UcF(const float* __restrict__ Uc) {
    int fid = blockIdx.x * blockDim.x + threadIdx.x;   // 262144
    int nt = fid >> 11, kc = (fid >> 5) & 63, lane = fid & 31;
    int n = nt * 8 + (lane >> 2);
    int k0 = kc * 16 + (lane & 3) * 2;
    g_UcF[fid] = make_uint2(
        pack2hf(Uc[(k0 + 0) * NU + n], Uc[(k0 + 1) * NU + n]),
        pack2hf(Uc[(k0 + 8) * NU + n], Uc[(k0 + 9) * NU + n]));
}

__global__ void pack_h_init(const float* __restrict__ h0) {
    int i = blockIdx.x * blockDim.x + threadIdx.x;     // 65536
    if (i < NB * NU) g_h[i] = h0[i];
    if (i < 4 * 64 * 32) {                              // h fragments
        int lane = i & 31, kc = (i >> 5) & 63, m16t = i >> 11;
        int r0 = m16t * 16 + (lane >> 2);
        int c0 = kc * 16 + (lane & 3) * 2;
        g_hF[i] = make_uint4(
            pack2hf(h0[r0 * NU + c0],           h0[r0 * NU + c0 + 1]),
            pack2hf(h0[(r0 + 8) * NU + c0],     h0[(r0 + 8) * NU + c0 + 1]),
            pack2hf(h0[r0 * NU + c0 + 8],       h0[r0 * NU + c0 + 9]),
            pack2hf(h0[(r0 + 8) * NU + c0 + 8], h0[(r0 + 8) * NU + c0 + 9]));
    }
}

// ------------------------- frag-direct precompute GEMM (single f16) ----------
__global__ __launch_bounds__(256) void gemm_pre_f() {
    const int tid = threadIdx.x;
    const int wid = tid >> 5, lane = tid & 31;
    const int wm = wid >> 2, wn = wid & 3;
    const int bn = blockIdx.x, bm = blockIdx.y;

    float acc[4][4][4];
#pragma unroll
    for (int i = 0; i < 4; i++)
#pragma unroll
        for (int j = 0; j < 4; j++)
#pragma unroll
            for (int k = 0; k < 4; k++) acc[i][j][k] = 0.0f;

    const uint4* ap = g_AF + ((size_t)(bm * 8 + wm * 4) * 128) * 32 + lane;
    const uint2* bp = g_WF + ((size_t)(bn * 16 + wn * 4) * 128) * 32 + lane;

    for (int kc = 0; kc < 128; kc++) {
        uint4 af[4];
        uint2 bf[4];
#pragma unroll
        for (int mi = 0; mi < 4; mi++) af[mi] = ap[(size_t)(mi * 128 + kc) * 32];
#pragma unroll
        for (int ni = 0; ni < 4; ni++) bf[ni] = bp[(size_t)(ni * 128 + kc) * 32];
#pragma unroll
        for (int mi = 0; mi < 4; mi++)
#pragma unroll
            for (int ni = 0; ni < 4; ni++)
                MMA_F16(acc[mi][ni], af[mi].x, af[mi].y, af[mi].z, af[mi].w,
                        bf[ni].x, bf[ni].y);
    }

#pragma unroll
    for (int mi = 0; mi < 4; mi++) {
        int mA = bm * 128 + wm * 64 + mi * 16 + (lane >> 2);
        int mB = mA + 8;
        int bA = mA >> 8, tA = mA & 255;
        int bB = mB >> 8, tB = mB & 255;
        float* oA = g_G + (size_t)(tA * NB + bA) * N3;
        float* oB = g_G + (size_t)(tB * NB + bB) * N3;
        int colb = bn * 128 + wn * 32 + (lane & 3) * 2;
#pragma unroll
        for (int ni = 0; ni < 4; ni++) {
            int c = colb + ni * 8;
            *(float2*)(oA + c) = make_float2(acc[mi][ni][0], acc[mi][ni][1]);
            *(float2*)(oB + c) = make_float2(acc[mi][ni][2], acc[mi][ni][3]);
        }
    }
}

// ------------------------- persistent recurrent kernel -----------------------
// U single-f16 (lo terms dropped): MMAs/step halved. Flat barrier (R14 proven).
__global__ __launch_bounds__(256, 1) void recurrent(float* __restrict__ out) {
    extern __shared__ __align__(16) uint2 dsm[];
    uint2* sU = dsm;                                   // [0,2048): b0, [2048,4096): b1, [4096,6144): uc
    float* sred = (float*)(dsm + 6144);                // 8KB reduce buffer
    const int bx = blockIdx.x;
    const int tid = threadIdx.x;
    const int wid = tid >> 5, lane = tid & 31;
    const int wm = wid >> 1, ws = wid & 1;
    const int erow = wm * 16 + (lane >> 2);
    const int ecol2 = (lane & 3) * 2;
    const int eb = tid >> 2, ejp = tid & 3;            // phase B final mapping

    // ---- stage U fragments into smem (once) ----
    {
        const uint2* u0 = g_UrzF + (size_t)(bx * 2 + 0) * 2048;
        const uint2* u1 = g_UrzF + (size_t)(bx * 2 + 1) * 2048;
        const uint2* uc = g_UcF + (size_t)bx * 2048;
#pragma unroll
        for (int i = 0; i < 8; i++) {
            int idx = i * 256 + tid;
            sU[idx] = u0[idx];
            sU[2048 + idx] = u1[idx];
            sU[4096 + idx] = uc[idx];
        }
    }
    __syncthreads();

    const int colg = bx * 16 + ws * 8 + ecol2;
    const int j0 = bx * 8 + ejp * 2;
    float2 G0 = *(const float2*)&g_G[((size_t)0 * NB + erow) * N3 + colg];
    float2 G1 = *(const float2*)&g_G[((size_t)0 * NB + erow + 8) * N3 + colg];

    for (int t = 0; t < NTT; t++) {
        // ===== phase A: h @ [U_r|U_z], K-split over ws, fused act_rz =========
        float2 Gc, hv;
        {
            const uint4* afr = g_hF + (wm * 64) * 32 + lane;
            float2 h0v = make_float2(0.f, 0.f), h1v = make_float2(0.f, 0.f);
            if (bx < 64) {
                h0v = __ldcg((const float2*)&g_h[erow * NU + colg]);
                h1v = __ldcg((const float2*)&g_h[(erow + 8) * NU + colg]);
            }
            float a0[4] = {0.f, 0.f, 0.f, 0.f};
            float a1[4] = {0.f, 0.f, 0.f, 0.f};
#pragma unroll 4
            for (int kc = 0; kc < 32; kc++) {
                int kk = ws * 32 + kc;
                uint4 av = __ldcg(&afr[kk * 32]);
                uint2 v0 = sU[kk * 32 + lane];
                uint2 v1 = sU[2048 + kk * 32 + lane];
                MMA_F16(a0, av.x, av.y, av.z, av.w, v0.x, v0.y);
                MMA_F16(a1, av.x, av.y, av.z, av.w, v1.x, v1.y);
            }
            *(float4*)&sred[((wm * 2 + 0) * 2 + ws) * 128 + lane * 4] =
                make_float4(a0[0], a0[1], a0[2], a0[3]);
            *(float4*)&sred[((wm * 2 + 1) * 2 + ws) * 128 + lane * 4] =
                make_float4(a1[0], a1[1], a1[2], a1[3]);
            __syncthreads();
            float4 p0 = *(const float4*)&sred[((wm * 2 + ws) * 2 + 0) * 128 + lane * 4];
            float4 p1 = *(const float4*)&sred[((wm * 2 + ws) * 2 + 1) * 128 + lane * 4];
            float s00 = p0.x + p1.x + G0.x, s01 = p0.y + p1.y + G0.y;
            float s10 = p0.z + p1.z + G1.x, s11 = p0.w + p1.w + G1.y;
            if (bx < 64) {                              // r gate -> a2 frags
                float a0v = h0v.x * hsig(s00), a1v = h0v.y * hsig(s01);
                float a2v = h1v.x * hsig(s10), a3v = h1v.y * hsig(s11);
                uint2* dst = (uint2*)&g_a2F[(wm * 64 + bx) * 32 + lane];
                dst[ws] = make_uint2(pack2hf(a0v, a1v), pack2hf(a2v, a3v));
            } else {                                    // z gate
                int j = colg - 1024;
                *(float2*)&g_z[erow * NU + j] = make_float2(hsig(s00), hsig(s01));
                *(float2*)&g_z[(erow + 8) * NU + j] = make_float2(hsig(s10), hsig(s11));
            }
            Gc = *(const float2*)&g_G[((size_t)t * NB + eb) * N3 + 2048 + j0];
            hv = __ldcg((const float2*)&g_h[eb * NU + j0]);
        }
        grid_bar();
        // ===== phase B: (h*r) @ U, cols bx*8..+8, fused act_h ================
        {
            const uint4* afr = g_a2F + (wm * 64) * 32 + lane;
            float2 zv = __ldcg((const float2*)&g_z[eb * NU + j0]);
            float ae[4] = {0.f, 0.f, 0.f, 0.f}, ao[4] = {0.f, 0.f, 0.f, 0.f};
#pragma unroll 4
            for (int kc = 0; kc < 32; kc += 2) {
                int kk0 = ws * 32 + kc, kk1 = kk0 + 1;
                uint4 av0 = __ldcg(&afr[kk0 * 32]);
                uint4 av1 = __ldcg(&afr[kk1 * 32]);
                uint2 bv0 = sU[4096 + kk0 * 32 + lane];
                uint2 bv1 = sU[4096 + kk1 * 32 + lane];
                MMA_F16(ae, av0.x, av0.y, av0.z, av0.w, bv0.x, bv0.y);
                MMA_F16(ao, av1.x, av1.y, av1.z, av1.w, bv1.x, bv1.y);
            }
            *(float2*)&sred[(ws * 64 + erow) * 8 + ecol2] =
                make_float2(ae[0] + ao[0], ae[1] + ao[1]);
            *(float2*)&sred[(ws * 64 + erow + 8) * 8 + ecol2] =
                make_float2(ae[2] + ao[2], ae[3] + ao[3]);
            __syncthreads();
            float s0 = sred[eb * 8 + ejp * 2]     + sred[(64 + eb) * 8 + ejp * 2]     + Gc.x;
            float s1 = sred[eb * 8 + ejp * 2 + 1] + sred[(64 + eb) * 8 + ejp * 2 + 1] + Gc.y;
            float hn0 = (1.0f - zv.x) * hv.x + zv.x * tanhf(s0);
            float hn1 = (1.0f - zv.y) * hv.y + zv.y * tanhf(s1);
            *(float2*)&g_h[eb * NU + j0] = make_float2(hn0, hn1);
            *(float2*)&out[((size_t)eb * NTT + t) * NU + j0] = make_float2(hn0, hn1);
            int comp = ((eb >> 3) & 1) | ((bx & 1) << 1);
            ((uint32_t*)&g_hF[((eb >> 4) * 64 + (bx >> 1)) * 32 + (((eb & 7) << 2) | ejp)])[comp]
                = pack2hf(hn0, hn1);
            int tn = (t + 1 < NTT) ? t + 1 : t;
            G0 = *(const float2*)&g_G[((size_t)tn * NB + erow) * N3 + colg];
            G1 = *(const float2*)&g_G[((size_t)tn * NB + erow + 8) * N3 + colg];
        }
        grid_bar();
    }
}

// ------------------------- launch -------------------------------------------
#define REC_SMEM (6144 * 8 + 8192)

extern "C" void kernel_launch(void* const* d_in, const int* in_sizes, int n_in,
                              void* d_out, int out_size) {
    const float* all = (const float*)d_in[0];
    const float* h0  = (const float*)d_in[1];
    const float* Wr  = (const float*)d_in[2];
    const float* Ur  = (const float*)d_in[3];
    const float* Cr  = (const float*)d_in[4];
    const float* Wz  = (const float*)d_in[5];
    const float* Uz  = (const float*)d_in[6];
    const float* Cz  = (const float*)d_in[7];
    const float* Wc  = (const float*)d_in[8];
    const float* Uc  = (const float*)d_in[9];
    const float* Cc  = (const float*)d_in[10];
    float* out = (float*)d_out;

    static int smem_set = 0;
    if (!smem_set) {
        cudaFuncSetAttribute(recurrent, cudaFuncAttributeMaxDynamicSharedMemorySize, REC_SMEM);
        smem_set = 1;
    }

    pack_AF<<<16384, 256>>>(all);
    pack_WF<<<6144, 256>>>(Wr, Cr, Wz, Cz, Wc, Cc);
    pack_UrzF<<<2048, 256>>>(Ur, Uz);
    pack_UcF<<<1024, 256>>>(Uc);
    pack_h_init<<<256, 256>>>(h0);
    gemm_pre_f<<<dim3(24, 128), 256>>>();
    recurrent<<<NBLK, 256, REC_SMEM>>>(out);
}